// round 2
// baseline (speedup 1.0000x reference)
#include <cuda_runtime.h>
#include <cuda_bf16.h>
#include <cstdint>

#define BIMG 16
#define AANC 65536
#define GGT  32
#define CAP  8192

// ---------------- device scratch (static, no allocations) ----------------
__device__ unsigned            gNumPos[BIMG];
__device__ double              gLocSum[BIMG];
__device__ double              gPosBce[BIMG];
__device__ double              gNegSum[BIMG];
__device__ unsigned            gPredCnt[BIMG];
__device__ double              gIouSum;
__device__ unsigned            gIouCnt;
__device__ unsigned long long  gBestGt[BIMG * GGT];      // packed (iou_bits<<32)|(65535-a)
__device__ float               gNegBce[BIMG * AANC];     // 4MB
__device__ unsigned            gHist[BIMG * 65536];      // 4MB, 16-bit-prefix histogram
__device__ unsigned            gPrefix[BIMG];            // selected 16-bit bin (or 0xFFFFFFFF)
__device__ unsigned            gRem[BIMG];                // count needed from that bin
__device__ unsigned            gCandCnt[BIMG];
__device__ unsigned            gCand[BIMG * CAP];

// ---------------- helpers ----------------
__device__ __forceinline__ float sl1(float d) {
    return d < 1.0f ? 0.5f * d * d : d - 0.5f;
}

__device__ __forceinline__ float loc_loss4(float4 P, float4 M) {
    float dcx = fabsf((P.x + P.z) * 0.5f - (M.x + M.z) * 0.5f);
    float dcy = fabsf((P.y + P.w) * 0.5f - (M.y + M.w) * 0.5f);
    float dw  = fabsf((P.z - P.x) - (M.z - M.x));
    float dh  = fabsf((P.w - P.y) - (M.w - M.y));
    return sl1(dcx) + sl1(dcy) + sl1(dw) + sl1(dh);
}

// ---------------- KZ: zero the 4MB histogram ----------------
__global__ void kz_hist() {
    int i = blockIdx.x * 256 + threadIdx.x;          // 262144 threads, uint4 each
    ((uint4*)gHist)[i] = make_uint4(0u, 0u, 0u, 0u);
}

// ---------------- K0: reset accumulators ----------------
__global__ void k0_reset() {
    int i = threadIdx.x;
    if (i < BIMG) {
        gNumPos[i] = 0u; gLocSum[i] = 0.0; gPosBce[i] = 0.0;
        gNegSum[i] = 0.0; gPredCnt[i] = 0u; gCandCnt[i] = 0u;
    }
    if (i == BIMG) { gIouSum = 0.0; gIouCnt = 0u; }
    if (i < BIMG * GGT) gBestGt[i] = 65535ULL;   // iou=0, anchor idx 0
}

// ---------------- K1: main IoU + per-anchor pass (+ fused hist) ----------------
__global__ void __launch_bounds__(256) k1_main(
    const float4* __restrict__ bbox,      // [B,A] float4
    const float*  __restrict__ conf,      // [B,A]
    const float4* __restrict__ anchors,   // [A] float4
    const float4* __restrict__ gt)        // [B,G] float4
{
    __shared__ float4 sGt[GGT];
    __shared__ float  sAreaG[GGT];
    __shared__ unsigned long long sBest[GGT];

    const int b = blockIdx.y;
    const int a = blockIdx.x * 256 + threadIdx.x;
    const int t = threadIdx.x;
    const int lane = t & 31;

    if (t < GGT) {
        float4 g = gt[b * GGT + t];
        sGt[t] = g;
        sAreaG[t] = (g.z - g.x) * (g.w - g.y);
        sBest[t] = 65535ULL;
    }
    __syncthreads();

    const float4 an = anchors[a];
    const float areaA = (an.z - an.x) * (an.w - an.y);

    float bestv = -1.0f;
    int   besti = 0;

    #pragma unroll 8
    for (int g = 0; g < GGT; ++g) {
        float4 G = sGt[g];
        float ltx = fmaxf(an.x, G.x);
        float lty = fmaxf(an.y, G.y);
        float rbx = fminf(an.z, G.z);
        float rby = fminf(an.w, G.w);
        float w = fmaxf(rbx - ltx, 0.0f);
        float h = fmaxf(rby - lty, 0.0f);
        float inter = w * h;
        float uni = areaA + sAreaG[g] - inter;
        float iou = inter / (uni + 1e-6f);
        if (iou > bestv) { bestv = iou; besti = g; }
        unsigned ib = __float_as_uint(iou);
        // pre-filtered per-gt best-anchor update (stale read only causes an extra atomic)
        if ((unsigned)(sBest[g] >> 32) < ib) {
            atomicMax(&sBest[g],
                      ((unsigned long long)ib << 32) | (unsigned long long)(65535u - (unsigned)a));
        }
    }

    const float p = conf[b * AANC + a];
    const bool pos0 = bestv > 0.5f;

    float bceNeg = fminf(-log1pf(-p), 100.0f);
    gNegBce[b * AANC + a] = pos0 ? 0.0f : bceNeg;
    if (!pos0) {
        // fused 16-bit-prefix histogram for top-k select
        atomicAdd(&gHist[(b << 16) + (__float_as_uint(bceNeg) >> 16)], 1u);
    }

    unsigned mPred = __ballot_sync(0xffffffffu, p > 0.5f);
    unsigned mPos  = __ballot_sync(0xffffffffu, pos0);
    if (lane == 0) {
        if (mPred) atomicAdd(&gPredCnt[b], (unsigned)__popc(mPred));
        if (mPos)  atomicAdd(&gNumPos[b],  (unsigned)__popc(mPos));
    }

    if (pos0) {
        float4 M = sGt[besti];
        float4 P = bbox[b * AANC + a];
        float loc = loc_loss4(P, M);
        atomicAdd(&gLocSum[b], (double)loc);
        atomicAdd(&gPosBce[b], (double)fminf(-logf(p), 100.0f));
    }

    if (b == BIMG - 1) {
        float v = bestv > 0.0f ? bestv : 0.0f;
        #pragma unroll
        for (int o = 16; o; o >>= 1) v += __shfl_down_sync(0xffffffffu, v, o);
        unsigned mI = __ballot_sync(0xffffffffu, bestv > 0.0f);
        if (lane == 0) {
            if (v != 0.0f) atomicAdd(&gIouSum, (double)v);
            if (mI) atomicAdd(&gIouCnt, (unsigned)__popc(mI));
        }
    }

    __syncthreads();
    if (t < GGT) atomicMax(&gBestGt[b * GGT + t], sBest[t]);
}

// ---------------- K3: scatter (best-anchor-per-gt) fixup ----------------
__global__ void k3_fixup(
    const float4* __restrict__ bbox,
    const float*  __restrict__ conf,
    const float4* __restrict__ anchors,
    const float4* __restrict__ gt)
{
    const int b = blockIdx.x;      // 16 blocks
    const int g = threadIdx.x;     // 32 threads
    __shared__ int sIdx[GGT];

    unsigned long long pk = gBestGt[b * GGT + g];
    int a = 65535 - (int)(pk & 0xffffffffu);
    sIdx[g] = a;
    __syncwarp();

    // dedupe: lowest g owns the anchor
    bool owner = true;
    for (int j = 0; j < g; ++j)
        if (sIdx[j] == a) owner = false;
    if (!owner) return;

    // recompute this anchor's best-over-gt iou + matched gt
    float4 an = anchors[a];
    float areaA = (an.z - an.x) * (an.w - an.y);
    float bestv = -1.0f;
    float4 Mb = gt[b * GGT];
    for (int j = 0; j < GGT; ++j) {
        float4 G = gt[b * GGT + j];
        float ltx = fmaxf(an.x, G.x);
        float lty = fmaxf(an.y, G.y);
        float rbx = fminf(an.z, G.z);
        float rby = fminf(an.w, G.w);
        float w = fmaxf(rbx - ltx, 0.0f);
        float h = fmaxf(rby - lty, 0.0f);
        float inter = w * h;
        float areaG = (G.z - G.x) * (G.w - G.y);
        float uni = areaA + areaG - inter;
        float iou = inter / (uni + 1e-6f);
        if (iou > bestv) { bestv = iou; Mb = G; }
    }
    if (bestv > 0.5f) return;   // already counted as positive in K1

    float p = conf[b * AANC + a];
    atomicAdd(&gNumPos[b], 1u);
    atomicAdd(&gPosBce[b], (double)fminf(-logf(p), 100.0f));
    float4 P = bbox[b * AANC + a];
    atomicAdd(&gLocSum[b], (double)loc_loss4(P, Mb));
    // remove from negative pool + keep histogram consistent
    float bceNeg = fminf(-log1pf(-p), 100.0f);
    atomicSub(&gHist[(b << 16) + (__float_as_uint(bceNeg) >> 16)], 1u);
    gNegBce[b * AANC + a] = 0.0f;
}

// ---------------- K4a: per-image threshold bin from histogram ----------------
__global__ void __launch_bounds__(1024) k4_thresh() {
    const int b = blockIdx.x;        // 16 blocks
    const int t = threadIdx.x;       // 1024 threads
    __shared__ unsigned csum[1024];

    const unsigned* __restrict__ h = &gHist[b << 16];
    unsigned s = 0;
    #pragma unroll 8
    for (int i = 0; i < 64; ++i) s += h[t * 64 + i];
    csum[t] = s;
    __syncthreads();

    if (t == 0) {
        unsigned np = gNumPos[b];
        unsigned k = min(3u * np, (unsigned)AANC - np);
        if (k == 0u) {
            gPrefix[b] = 0xFFFFFFFFu; gRem[b] = 0u;
        } else {
            unsigned acc = 0;
            int c = 1023;
            for (; c >= 0; --c) {
                if (acc + csum[c] >= k) break;
                acc += csum[c];
            }
            unsigned pre = 0xFFFFFFFFu, rem = 0u;
            for (int bin = c * 64 + 63; bin >= c * 64; --bin) {
                unsigned cc = h[bin];
                if (acc + cc >= k) { pre = (unsigned)bin; rem = k - acc; break; }
                acc += cc;
            }
            gPrefix[b] = pre; gRem[b] = rem;
        }
    }
}

// ---------------- K4b: grid-parallel sum above threshold + collect boundary ----------------
__global__ void __launch_bounds__(256) k4_collect() {
    const int b = blockIdx.y;
    const int t = threadIdx.x;
    const unsigned pre = gPrefix[b];
    const float4* __restrict__ nb = (const float4*)&gNegBce[b * AANC];
    const int v4base = (blockIdx.x * 256 + t) * 2;     // 2 float4 = 8 elems/thread

    double sum = 0.0;
    #pragma unroll
    for (int j = 0; j < 2; ++j) {
        float4 v = nb[v4base + j];
        float vv[4] = {v.x, v.y, v.z, v.w};
        #pragma unroll
        for (int c = 0; c < 4; ++c) {
            unsigned u = __float_as_uint(vv[c]);
            unsigned hb = u >> 16;
            if (hb > pre) sum += (double)vv[c];
            else if (hb == pre) {
                unsigned idx = atomicAdd(&gCandCnt[b], 1u);
                if (idx < CAP) gCand[b * CAP + idx] = u;
            }
        }
    }
    #pragma unroll
    for (int o = 16; o; o >>= 1) sum += __shfl_down_sync(0xffffffffu, sum, o);
    if ((t & 31) == 0 && sum != 0.0) atomicAdd(&gNegSum[b], sum);
}

// ---------------- K4c: exact low-16 radix select on boundary candidates ----------------
__global__ void __launch_bounds__(256) k4_select() {
    const int b = blockIdx.x;        // 16 blocks
    const int t = threadIdx.x;       // 256 threads
    __shared__ unsigned hist[256];
    __shared__ unsigned sSel, sRem;
    __shared__ double   wsum[8];

    const unsigned pre = gPrefix[b];
    if (pre == 0xFFFFFFFFu) return;
    const unsigned n = min(gCandCnt[b], (unsigned)CAP);
    unsigned rem = gRem[b];
    const unsigned* __restrict__ cd = &gCand[b * CAP];

    // round 1: bits [8:16)
    hist[t] = 0u; __syncthreads();
    for (unsigned i = t; i < n; i += 256) atomicAdd(&hist[(cd[i] >> 8) & 255u], 1u);
    __syncthreads();
    if (t == 0) {
        unsigned acc = 0;
        for (int bin = 255; bin >= 0; --bin) {
            unsigned c = hist[bin];
            if (acc + c >= rem) { sSel = (unsigned)bin; sRem = rem - acc; break; }
            acc += c;
        }
    }
    __syncthreads();
    const unsigned sel1 = sSel;
    rem = sRem;
    __syncthreads();

    // round 2: bits [0:8)
    hist[t] = 0u; __syncthreads();
    for (unsigned i = t; i < n; i += 256) {
        unsigned u = cd[i];
        if (((u >> 8) & 255u) == sel1) atomicAdd(&hist[u & 255u], 1u);
    }
    __syncthreads();
    if (t == 0) {
        unsigned acc = 0;
        for (int bin = 255; bin >= 0; --bin) {
            unsigned c = hist[bin];
            if (acc + c >= rem) { sSel = (unsigned)bin; sRem = rem - acc; break; }
            acc += c;
        }
    }
    __syncthreads();

    const unsigned vt = (pre << 16) | (sel1 << 8) | sSel;   // exact k-th value bits
    const unsigned remf = sRem;                             // ties at vt still needed

    double sum = 0.0;
    for (unsigned i = t; i < n; i += 256) {
        unsigned u = cd[i];
        if (u > vt) sum += (double)__uint_as_float(u);
    }
    #pragma unroll
    for (int o = 16; o; o >>= 1) sum += __shfl_down_sync(0xffffffffu, sum, o);
    if ((t & 31) == 0) wsum[t >> 5] = sum;
    __syncthreads();
    if (t == 0) {
        double s = 0.0;
        for (int w = 0; w < 8; ++w) s += wsum[w];
        s += (double)remf * (double)__uint_as_float(vt);
        atomicAdd(&gNegSum[b], s);
    }
}

// ---------------- K5: finalize ----------------
__global__ void k5_final(float* __restrict__ out) {
    unsigned npTot = 0;
    double loc = 0.0, confl = 0.0, cpen = 0.0;
    for (int b = 0; b < BIMG; ++b) {
        npTot += gNumPos[b];
        loc   += gLocSum[b];
        confl += gNegSum[b] + gPosBce[b];
        float diff = fabsf((float)((int)gPredCnt[b] - GGT));
        float pen = (diff <= 3.0f) ? diff * 0.2f
                                   : 0.6f + 0.2f * logf(fmaxf(diff - 2.0f, 1.0f));
        cpen += (double)pen;
    }
    float npos = (float)(npTot > 0u ? npTot : 1u);
    float tl = (float)loc / npos;
    float tc = (float)confl / npos;
    float tcnt = (float)(cpen) / (float)BIMG;
    float mean = (gIouCnt > 0u) ? (float)(gIouSum / (double)gIouCnt) : 0.1f;
    float iq = fminf(fmaxf(1.0f - mean, 0.1f), 0.9f);
    float total = (1.0f + iq) * tl + 1.0f * tc + 0.2f * tcnt;
    out[0] = total;
    out[1] = tc;
    out[2] = tl;
    out[3] = tcnt;
    out[4] = mean;
}

// ---------------- launch ----------------
extern "C" void kernel_launch(void* const* d_in, const int* in_sizes, int n_in,
                              void* d_out, int out_size) {
    const float4* bbox    = (const float4*)d_in[0];   // [16,65536,4]
    const float*  conf    = (const float*)d_in[1];    // [16,65536]
    const float4* anchors = (const float4*)d_in[2];   // [65536,4]
    const float4* gt      = (const float4*)d_in[3];   // [16,32,4]
    float* out = (float*)d_out;

    kz_hist<<<BIMG * 65536 / (256 * 4), 256>>>();
    k0_reset<<<1, 512>>>();
    k1_main<<<dim3(AANC / 256, BIMG), 256>>>(bbox, conf, anchors, gt);
    k3_fixup<<<BIMG, GGT>>>(bbox, conf, anchors, gt);
    k4_thresh<<<BIMG, 1024>>>();
    k4_collect<<<dim3(AANC / 2048, BIMG), 256>>>();
    k4_select<<<BIMG, 256>>>();
    k5_final<<<1, 1>>>(out);
}

// round 3
// speedup vs baseline: 1.5815x; 1.5815x over previous
#include <cuda_runtime.h>
#include <cuda_bf16.h>
#include <cstdint>

#define BIMG 16
#define AANC 65536
#define GGT  32
#define CAP  8192

// ---------------- device scratch (static, no allocations) ----------------
__device__ unsigned            gNumPos[BIMG];
__device__ double              gLocSum[BIMG];
__device__ double              gPosBce[BIMG];
__device__ double              gNegSum[BIMG];
__device__ unsigned            gPredCnt[BIMG];
__device__ double              gIouSum;
__device__ unsigned            gIouCnt;
__device__ unsigned long long  gBestGt[BIMG * GGT];      // packed (iou_bits<<32)|(65535-a)
__device__ float               gNegBce[BIMG * AANC];     // 4MB
__device__ unsigned            gHist[BIMG * 65536];      // 4MB, 16-bit-prefix histogram
__device__ unsigned            gPrefix[BIMG];            // selected 16-bit bin (or 0xFFFFFFFF)
__device__ unsigned            gRem[BIMG];                // count needed from that bin
__device__ unsigned            gCandCnt[BIMG];
__device__ unsigned            gCand[BIMG * CAP];

// ---------------- helpers ----------------
__device__ __forceinline__ float sl1(float d) {
    return d < 1.0f ? 0.5f * d * d : d - 0.5f;
}

__device__ __forceinline__ float loc_loss4(float4 P, float4 M) {
    float dcx = fabsf((P.x + P.z) * 0.5f - (M.x + M.z) * 0.5f);
    float dcy = fabsf((P.y + P.w) * 0.5f - (M.y + M.w) * 0.5f);
    float dw  = fabsf((P.z - P.x) - (M.z - M.x));
    float dh  = fabsf((P.w - P.y) - (M.w - M.y));
    return sl1(dcx) + sl1(dcy) + sl1(dw) + sl1(dh);
}

// ---------------- KZ: zero the 4MB histogram ----------------
__global__ void kz_hist() {
    int i = blockIdx.x * 256 + threadIdx.x;          // 262144 threads, uint4 each
    ((uint4*)gHist)[i] = make_uint4(0u, 0u, 0u, 0u);
}

// ---------------- K0: reset accumulators ----------------
__global__ void k0_reset() {
    int i = threadIdx.x;
    if (i < BIMG) {
        gNumPos[i] = 0u; gLocSum[i] = 0.0; gPosBce[i] = 0.0;
        gNegSum[i] = 0.0; gPredCnt[i] = 0u; gCandCnt[i] = 0u;
    }
    if (i == BIMG) { gIouSum = 0.0; gIouCnt = 0u; }
    if (i < BIMG * GGT) gBestGt[i] = 65535ULL;   // iou=0, anchor idx 0
}

// ---------------- K1: main IoU + per-anchor pass (+ fused hist) ----------------
__global__ void __launch_bounds__(256) k1_main(
    const float4* __restrict__ bbox,      // [B,A] float4
    const float*  __restrict__ conf,      // [B,A]
    const float4* __restrict__ anchors,   // [A] float4
    const float4* __restrict__ gt)        // [B,G] float4
{
    __shared__ float4 sGt[GGT];
    __shared__ float  sAreaG[GGT];
    __shared__ unsigned long long sBest[GGT];

    const int b = blockIdx.y;
    const int a = blockIdx.x * 256 + threadIdx.x;
    const int t = threadIdx.x;
    const int lane = t & 31;

    if (t < GGT) {
        float4 g = gt[b * GGT + t];
        sGt[t] = g;
        sAreaG[t] = (g.z - g.x) * (g.w - g.y);
        sBest[t] = 65535ULL;
    }
    __syncthreads();

    const float4 an = anchors[a];
    const float areaA = (an.z - an.x) * (an.w - an.y);

    float bestv = -1.0f;
    int   besti = 0;

    #pragma unroll 8
    for (int g = 0; g < GGT; ++g) {
        float4 G = sGt[g];
        float ltx = fmaxf(an.x, G.x);
        float lty = fmaxf(an.y, G.y);
        float rbx = fminf(an.z, G.z);
        float rby = fminf(an.w, G.w);
        float w = fmaxf(rbx - ltx, 0.0f);
        float h = fmaxf(rby - lty, 0.0f);
        float inter = w * h;
        float uni = areaA + sAreaG[g] - inter;
        float iou = inter / (uni + 1e-6f);
        if (iou > bestv) { bestv = iou; besti = g; }
        unsigned ib = __float_as_uint(iou);
        // pre-filtered per-gt best-anchor update (stale read only causes an extra atomic)
        if ((unsigned)(sBest[g] >> 32) < ib) {
            atomicMax(&sBest[g],
                      ((unsigned long long)ib << 32) | (unsigned long long)(65535u - (unsigned)a));
        }
    }

    const float p = conf[b * AANC + a];
    const bool pos0 = bestv > 0.5f;

    float bceNeg = fminf(-log1pf(-p), 100.0f);
    gNegBce[b * AANC + a] = pos0 ? 0.0f : bceNeg;
    if (!pos0) {
        // fused 16-bit-prefix histogram for top-k select
        atomicAdd(&gHist[(b << 16) + (__float_as_uint(bceNeg) >> 16)], 1u);
    }

    unsigned mPred = __ballot_sync(0xffffffffu, p > 0.5f);
    unsigned mPos  = __ballot_sync(0xffffffffu, pos0);
    if (lane == 0) {
        if (mPred) atomicAdd(&gPredCnt[b], (unsigned)__popc(mPred));
        if (mPos)  atomicAdd(&gNumPos[b],  (unsigned)__popc(mPos));
    }

    if (pos0) {
        float4 M = sGt[besti];
        float4 P = bbox[b * AANC + a];
        float loc = loc_loss4(P, M);
        atomicAdd(&gLocSum[b], (double)loc);
        atomicAdd(&gPosBce[b], (double)fminf(-logf(p), 100.0f));
    }

    if (b == BIMG - 1) {
        float v = bestv > 0.0f ? bestv : 0.0f;
        #pragma unroll
        for (int o = 16; o; o >>= 1) v += __shfl_down_sync(0xffffffffu, v, o);
        unsigned mI = __ballot_sync(0xffffffffu, bestv > 0.0f);
        if (lane == 0) {
            if (v != 0.0f) atomicAdd(&gIouSum, (double)v);
            if (mI) atomicAdd(&gIouCnt, (unsigned)__popc(mI));
        }
    }

    __syncthreads();
    if (t < GGT) atomicMax(&gBestGt[b * GGT + t], sBest[t]);
}

// ---------------- K3: scatter (best-anchor-per-gt) fixup ----------------
__global__ void k3_fixup(
    const float4* __restrict__ bbox,
    const float*  __restrict__ conf,
    const float4* __restrict__ anchors,
    const float4* __restrict__ gt)
{
    const int b = blockIdx.x;      // 16 blocks
    const int g = threadIdx.x;     // 32 threads
    __shared__ int sIdx[GGT];

    unsigned long long pk = gBestGt[b * GGT + g];
    int a = 65535 - (int)(pk & 0xffffffffu);
    sIdx[g] = a;
    __syncwarp();

    // dedupe: lowest g owns the anchor
    bool owner = true;
    for (int j = 0; j < g; ++j)
        if (sIdx[j] == a) owner = false;
    if (!owner) return;

    // recompute this anchor's best-over-gt iou + matched gt
    float4 an = anchors[a];
    float areaA = (an.z - an.x) * (an.w - an.y);
    float bestv = -1.0f;
    float4 Mb = gt[b * GGT];
    for (int j = 0; j < GGT; ++j) {
        float4 G = gt[b * GGT + j];
        float ltx = fmaxf(an.x, G.x);
        float lty = fmaxf(an.y, G.y);
        float rbx = fminf(an.z, G.z);
        float rby = fminf(an.w, G.w);
        float w = fmaxf(rbx - ltx, 0.0f);
        float h = fmaxf(rby - lty, 0.0f);
        float inter = w * h;
        float areaG = (G.z - G.x) * (G.w - G.y);
        float uni = areaA + areaG - inter;
        float iou = inter / (uni + 1e-6f);
        if (iou > bestv) { bestv = iou; Mb = G; }
    }
    if (bestv > 0.5f) return;   // already counted as positive in K1

    float p = conf[b * AANC + a];
    atomicAdd(&gNumPos[b], 1u);
    atomicAdd(&gPosBce[b], (double)fminf(-logf(p), 100.0f));
    float4 P = bbox[b * AANC + a];
    atomicAdd(&gLocSum[b], (double)loc_loss4(P, Mb));
    // remove from negative pool + keep histogram consistent
    float bceNeg = fminf(-log1pf(-p), 100.0f);
    atomicSub(&gHist[(b << 16) + (__float_as_uint(bceNeg) >> 16)], 1u);
    gNegBce[b * AANC + a] = 0.0f;
}

// ---------------- K4a: per-image threshold bin from histogram ----------------
__global__ void __launch_bounds__(1024) k4_thresh() {
    const int b = blockIdx.x;        // 16 blocks
    const int t = threadIdx.x;       // 1024 threads
    __shared__ unsigned csum[1024];

    const unsigned* __restrict__ h = &gHist[b << 16];
    unsigned s = 0;
    #pragma unroll 8
    for (int i = 0; i < 64; ++i) s += h[t * 64 + i];
    csum[t] = s;
    __syncthreads();

    if (t == 0) {
        unsigned np = gNumPos[b];
        unsigned k = min(3u * np, (unsigned)AANC - np);
        if (k == 0u) {
            gPrefix[b] = 0xFFFFFFFFu; gRem[b] = 0u;
        } else {
            unsigned acc = 0;
            int c = 1023;
            for (; c >= 0; --c) {
                if (acc + csum[c] >= k) break;
                acc += csum[c];
            }
            unsigned pre = 0xFFFFFFFFu, rem = 0u;
            for (int bin = c * 64 + 63; bin >= c * 64; --bin) {
                unsigned cc = h[bin];
                if (acc + cc >= k) { pre = (unsigned)bin; rem = k - acc; break; }
                acc += cc;
            }
            gPrefix[b] = pre; gRem[b] = rem;
        }
    }
}

// ---------------- K4b: grid-parallel sum above threshold + collect boundary ----------------
__global__ void __launch_bounds__(256) k4_collect() {
    const int b = blockIdx.y;
    const int t = threadIdx.x;
    const unsigned pre = gPrefix[b];
    const float4* __restrict__ nb = (const float4*)&gNegBce[b * AANC];
    const int v4base = (blockIdx.x * 256 + t) * 2;     // 2 float4 = 8 elems/thread

    double sum = 0.0;
    #pragma unroll
    for (int j = 0; j < 2; ++j) {
        float4 v = nb[v4base + j];
        float vv[4] = {v.x, v.y, v.z, v.w};
        #pragma unroll
        for (int c = 0; c < 4; ++c) {
            unsigned u = __float_as_uint(vv[c]);
            unsigned hb = u >> 16;
            if (hb > pre) sum += (double)vv[c];
            else if (hb == pre) {
                unsigned idx = atomicAdd(&gCandCnt[b], 1u);
                if (idx < CAP) gCand[b * CAP + idx] = u;
            }
        }
    }
    #pragma unroll
    for (int o = 16; o; o >>= 1) sum += __shfl_down_sync(0xffffffffu, sum, o);
    if ((t & 31) == 0 && sum != 0.0) atomicAdd(&gNegSum[b], sum);
}

// ---------------- K4c: exact low-16 radix select on boundary candidates ----------------
__global__ void __launch_bounds__(256) k4_select() {
    const int b = blockIdx.x;        // 16 blocks
    const int t = threadIdx.x;       // 256 threads
    __shared__ unsigned hist[256];
    __shared__ unsigned sSel, sRem;
    __shared__ double   wsum[8];

    const unsigned pre = gPrefix[b];
    if (pre == 0xFFFFFFFFu) return;
    const unsigned n = min(gCandCnt[b], (unsigned)CAP);
    unsigned rem = gRem[b];
    const unsigned* __restrict__ cd = &gCand[b * CAP];

    // round 1: bits [8:16)
    hist[t] = 0u; __syncthreads();
    for (unsigned i = t; i < n; i += 256) atomicAdd(&hist[(cd[i] >> 8) & 255u], 1u);
    __syncthreads();
    if (t == 0) {
        unsigned acc = 0;
        for (int bin = 255; bin >= 0; --bin) {
            unsigned c = hist[bin];
            if (acc + c >= rem) { sSel = (unsigned)bin; sRem = rem - acc; break; }
            acc += c;
        }
    }
    __syncthreads();
    const unsigned sel1 = sSel;
    rem = sRem;
    __syncthreads();

    // round 2: bits [0:8)
    hist[t] = 0u; __syncthreads();
    for (unsigned i = t; i < n; i += 256) {
        unsigned u = cd[i];
        if (((u >> 8) & 255u) == sel1) atomicAdd(&hist[u & 255u], 1u);
    }
    __syncthreads();
    if (t == 0) {
        unsigned acc = 0;
        for (int bin = 255; bin >= 0; --bin) {
            unsigned c = hist[bin];
            if (acc + c >= rem) { sSel = (unsigned)bin; sRem = rem - acc; break; }
            acc += c;
        }
    }
    __syncthreads();

    const unsigned vt = (pre << 16) | (sel1 << 8) | sSel;   // exact k-th value bits
    const unsigned remf = sRem;                             // ties at vt still needed

    double sum = 0.0;
    for (unsigned i = t; i < n; i += 256) {
        unsigned u = cd[i];
        if (u > vt) sum += (double)__uint_as_float(u);
    }
    #pragma unroll
    for (int o = 16; o; o >>= 1) sum += __shfl_down_sync(0xffffffffu, sum, o);
    if ((t & 31) == 0) wsum[t >> 5] = sum;
    __syncthreads();
    if (t == 0) {
        double s = 0.0;
        for (int w = 0; w < 8; ++w) s += wsum[w];
        s += (double)remf * (double)__uint_as_float(vt);
        atomicAdd(&gNegSum[b], s);
    }
}

// ---------------- K5: finalize ----------------
__global__ void k5_final(float* __restrict__ out) {
    unsigned npTot = 0;
    double loc = 0.0, confl = 0.0, cpen = 0.0;
    for (int b = 0; b < BIMG; ++b) {
        npTot += gNumPos[b];
        loc   += gLocSum[b];
        confl += gNegSum[b] + gPosBce[b];
        float diff = fabsf((float)((int)gPredCnt[b] - GGT));
        float pen = (diff <= 3.0f) ? diff * 0.2f
                                   : 0.6f + 0.2f * logf(fmaxf(diff - 2.0f, 1.0f));
        cpen += (double)pen;
    }
    float npos = (float)(npTot > 0u ? npTot : 1u);
    float tl = (float)loc / npos;
    float tc = (float)confl / npos;
    float tcnt = (float)(cpen) / (float)BIMG;
    float mean = (gIouCnt > 0u) ? (float)(gIouSum / (double)gIouCnt) : 0.1f;
    float iq = fminf(fmaxf(1.0f - mean, 0.1f), 0.9f);
    float total = (1.0f + iq) * tl + 1.0f * tc + 0.2f * tcnt;
    out[0] = total;
    out[1] = tc;
    out[2] = tl;
    out[3] = tcnt;
    out[4] = mean;
}

// ---------------- launch ----------------
extern "C" void kernel_launch(void* const* d_in, const int* in_sizes, int n_in,
                              void* d_out, int out_size) {
    const float4* bbox    = (const float4*)d_in[0];   // [16,65536,4]
    const float*  conf    = (const float*)d_in[1];    // [16,65536]
    const float4* anchors = (const float4*)d_in[2];   // [65536,4]
    const float4* gt      = (const float4*)d_in[3];   // [16,32,4]
    float* out = (float*)d_out;

    kz_hist<<<BIMG * 65536 / (256 * 4), 256>>>();
    k0_reset<<<1, 512>>>();
    k1_main<<<dim3(AANC / 256, BIMG), 256>>>(bbox, conf, anchors, gt);
    k3_fixup<<<BIMG, GGT>>>(bbox, conf, anchors, gt);
    k4_thresh<<<BIMG, 1024>>>();
    k4_collect<<<dim3(AANC / 2048, BIMG), 256>>>();
    k4_select<<<BIMG, 256>>>();
    k5_final<<<1, 1>>>(out);
}